// round 6
// baseline (speedup 1.0000x reference)
#include <cuda_runtime.h>

#define THREADS 256

// ---------- packed f32x2 helpers ----------
__device__ __forceinline__ unsigned long long pk2(float lo, float hi) {
    unsigned long long r;
    asm("mov.b64 %0, {%1, %2};" : "=l"(r) : "f"(lo), "f"(hi));
    return r;
}
__device__ __forceinline__ void upk2(unsigned long long v, float& lo, float& hi) {
    asm("mov.b64 {%0, %1}, %2;" : "=f"(lo), "=f"(hi) : "l"(v));
}
__device__ __forceinline__ void ffma2(unsigned long long& acc, unsigned long long a, unsigned long long b) {
    asm("fma.rn.f32x2 %0, %1, %2, %0;" : "+l"(acc) : "l"(a), "l"(b));
}
__device__ __forceinline__ unsigned long long mul2(unsigned long long a, unsigned long long b) {
    unsigned long long r; asm("mul.rn.f32x2 %0, %1, %2;" : "=l"(r) : "l"(a), "l"(b)); return r;
}
__device__ __forceinline__ unsigned long long add2(unsigned long long a, unsigned long long b) {
    unsigned long long r; asm("add.rn.f32x2 %0, %1, %2;" : "=l"(r) : "l"(a), "l"(b)); return r;
}
__device__ __forceinline__ float sqrt_ap(float x){ float r; asm("sqrt.approx.f32 %0, %1;" : "=f"(r) : "f"(x)); return r; }
__device__ __forceinline__ float rcp_ap (float x){ float r; asm("rcp.approx.f32 %0, %1;"  : "=f"(r) : "f"(x)); return r; }

// smem float offsets:
//  W (swizzled 16B chunks)  [4096]
//  S (A^T A sextets)        [768]
//  EI                       [128]
//  B                        [16]
//  M  [8][16*17]            [2176]
//  Y  [128][9 f32x2]        [2304]
#define SM_W  0
#define SM_S  4096
#define SM_EI 4864
#define SM_B  4992
#define SM_M  5008
#define SM_Y  7184
#define SMEM_FLOATS 9488

__global__ __launch_bounds__(THREADS, 2)
void ocae4(const float* __restrict__ eq,  const float* __restrict__ rei,
           const float* __restrict__ Wg,  const float* __restrict__ bias,
           const float* __restrict__ envdim, const float* __restrict__ envion,
           float* __restrict__ out)
{
    __shared__ float sm[SMEM_FLOATS];
    const int tid = threadIdx.x;
    const int s   = blockIdx.x & 1;
    const int b0  = (blockIdx.x >> 1) * 8;

    // ---------------- stage W (swizzled), S, EI, B ----------------
    {
        const float4* Wsrc = (const float4*)(Wg + (size_t)s * 4096);
        #pragma unroll
        for (int j = 0; j < 4; j++) {
            int id = tid + 256*j;             // 16B chunk id 0..1023
            float4 v = __ldg(Wsrc + id);
            int k = id >> 2, c = id & 3;
            int slot = ((k >> 1) << 3) + (((((k & 1) << 2) | c)) ^ ((k >> 2) & 7));
            *(float4*)(sm + SM_W + slot*4) = v;
        }
        if (tid < 128) {
            sm[SM_EI + tid] = envion[s*128 + tid];
            int ii = tid >> 4, oo = tid & 15;
            const float* A = envdim + s*1152 + ii*144 + oo*9;
            float a00=A[0],a01=A[1],a02=A[2], a10=A[3],a11=A[4],a12=A[5], a20=A[6],a21=A[7],a22=A[8];
            float s00 = a00*a00 + a10*a10 + a20*a20;
            float s11 = a01*a01 + a11*a11 + a21*a21;
            float s22 = a02*a02 + a12*a12 + a22*a22;
            float s01 = 2.f*(a00*a01 + a10*a11 + a20*a21);
            float s02 = 2.f*(a00*a02 + a10*a12 + a20*a22);
            float s12 = 2.f*(a01*a02 + a11*a12 + a21*a22);
            float* dst = sm + SM_S + (ii*8 + (oo>>1))*12 + (oo&1);
            dst[0]=s00; dst[2]=s11; dst[4]=s22; dst[6]=s01; dst[8]=s02; dst[10]=s12;
        }
        if (tid < 16) sm[SM_B + tid] = bias[s*16 + tid];
    }

    const int wid   = tid >> 5;
    const int lane  = tid & 31;
    const int rsub  = lane >> 3;     // row within warp group
    const int klane = lane & 7;      // k-lane

    // 8 swizzled W base pointers (immediate-foldable offsets inside the loop)
    const ulonglong2* wptr[2][4];
    #pragma unroll
    for (int e1 = 0; e1 < 2; e1++)
        #pragma unroll
        for (int c = 0; c < 4; c++)
            wptr[e1][c] = (const ulonglong2*)(sm + SM_W + klane*64 + ((((e1<<2)|c) ^ klane) << 2));

    __syncthreads();

    // ---------------- GEMM: 4 passes, split-K in warp ----------------
    const unsigned FULL = 0xffffffffu;
    #pragma unroll 1
    for (int p = 0; p < 4; p++) {
        const int rloc = p*32 + wid*4 + rsub;
        const size_t grow = ((size_t)(b0 + (rloc>>4)))*32 + s*16 + (rloc&15);
        const float4* xp = (const float4*)(eq + grow*256) + klane;

        float4 xv[8];
        #pragma unroll
        for (int q = 0; q < 8; q++) xv[q] = __ldg(xp + q*8);

        unsigned long long acc[8] = {0,0,0,0,0,0,0,0};
        #pragma unroll
        for (int q = 0; q < 8; q++) {
            float xa[4]; *(float4*)xa = xv[q];
            #pragma unroll
            for (int e = 0; e < 4; e++) {
                unsigned long long xx = pk2(xa[e], xa[e]);
                const int eo = q*128 + (e>>1)*8;   // ulonglong2 element offset
                #pragma unroll
                for (int c = 0; c < 4; c++) {
                    ulonglong2 wc = wptr[e&1][c][eo];
                    ffma2(acc[2*c],   xx, wc.x);
                    ffma2(acc[2*c+1], xx, wc.y);
                }
            }
        }
        // reduce over the 8 k-lanes
        #pragma unroll
        for (int off = 1; off < 8; off <<= 1)
            #pragma unroll
            for (int op = 0; op < 8; op++)
                acc[op] = add2(acc[op], __shfl_xor_sync(FULL, acc[op], off));
        // lane klane owns orbital-pair klane
        unsigned long long v = acc[0];
        #pragma unroll
        for (int op = 1; op < 8; op++) if (klane == op) v = acc[op];
        *(unsigned long long*)(sm + SM_Y + rloc*18 + klane*2) = v;
    }
    __syncthreads();

    // ---------------- env + M (2 threads per row, 4 op-pairs each) ----------------
    {
        const int r = tid >> 1;
        const int h = tid & 1;
        const size_t growr = ((size_t)(b0 + (r>>4)))*32 + s*16 + (r&15);
        float rv[24];
        {
            const float4* rp = (const float4*)(rei + growr*24);
            #pragma unroll
            for (int q = 0; q < 6; q++) *(float4*)(rv + q*4) = __ldg(rp + q);
        }
        unsigned long long ev[4] = {0,0,0,0};
        #pragma unroll
        for (int i = 0; i < 8; i++) {
            float r0 = rv[i*3], r1 = rv[i*3+1], r2 = rv[i*3+2];
            unsigned long long p00 = pk2(r0*r0, r0*r0);
            unsigned long long p11 = pk2(r1*r1, r1*r1);
            unsigned long long p22 = pk2(r2*r2, r2*r2);
            unsigned long long p01 = pk2(r0*r1, r0*r1);
            unsigned long long p02 = pk2(r0*r2, r0*r2);
            unsigned long long p12 = pk2(r1*r2, r1*r2);
            const float* Sb = sm + SM_S + i*96 + h*48;
            const unsigned long long* Eb = (const unsigned long long*)(sm + SM_EI) + i*8 + h*4;
            #pragma unroll
            for (int op = 0; op < 4; op++) {
                const ulonglong2* Sp = (const ulonglong2*)(Sb + op*12);
                ulonglong2 sA = Sp[0], sB = Sp[1], sC = Sp[2];
                unsigned long long q = 0ull;
                ffma2(q, sA.x, p00); ffma2(q, sA.y, p11); ffma2(q, sB.x, p22);
                ffma2(q, sB.y, p01); ffma2(q, sC.x, p02); ffma2(q, sC.y, p12);
                float q0, q1; upk2(q, q0, q1);
                float e0 = __expf(-sqrt_ap(fmaxf(q0, 0.f)));
                float e1 = __expf(-sqrt_ap(fmaxf(q1, 0.f)));
                ffma2(ev[op], pk2(e0, e1), Eb[op]);
            }
        }
        const int m = r >> 4, n = r & 15;
        float* Mb = sm + SM_M + m*272 + n;
        #pragma unroll
        for (int op = 0; op < 4; op++) {
            int gp = h*4 + op;
            unsigned long long y  = *(const unsigned long long*)(sm + SM_Y + r*18 + gp*2);
            unsigned long long bb = *(const unsigned long long*)(sm + SM_B + gp*2);
            unsigned long long mm = mul2(add2(y, bb), ev[op]);
            float m0, m1; upk2(mm, m0, m1);
            Mb[(2*gp)*17]   = m0;
            Mb[(2*gp+1)*17] = m1;
        }
    }
    __syncthreads();

    // ---------------- cofactors: register LU, warp wid -> matrix wid ----------------
    {
        const int o = lane & 15;             // row of A = M^T (upper segment redundant)
        float a[17];
        {
            const float* Ma = sm + SM_M + wid*272 + o*17;
            #pragma unroll
            for (int j = 0; j < 16; j++) a[j] = Ma[j];
            a[16] = (o == 0) ? 1.f : 0.f;    // rhs e0
        }
        float det = 1.f;

        #pragma unroll
        for (int k = 0; k < 16; k++) {
            float v = (o >= k) ? fabsf(a[k]) : -1.f;
            int   p = o;
            #pragma unroll
            for (int off = 8; off; off >>= 1) {
                float ov = __shfl_xor_sync(FULL, v, off, 16);
                int   oq = __shfl_xor_sync(FULL, p, off, 16);
                if (ov > v || (ov == v && oq < p)) { v = ov; p = oq; }
            }
            float pvk = __shfl_sync(FULL, a[k], p, 16);
            float kvk = __shfl_sync(FULL, a[k], k, 16);
            if (o == k) a[k] = pvk; else if (o == p) a[k] = kvk;
            det = (p != k) ? -det : det;
            det *= pvk;
            float mlt = (o > k) ? a[k] * rcp_ap(pvk) : 0.f;
            #pragma unroll
            for (int j = k + 1; j < 17; j++) {
                float pv = __shfl_sync(FULL, a[j], p, 16);
                float kv = __shfl_sync(FULL, a[j], k, 16);
                if (o == k) a[j] = pv; else if (o == p) a[j] = kv;
                a[j] -= mlt * pv;
            }
        }

        // back-substitution: U z = rhs
        float z = 0.f, rhs = a[16];
        #pragma unroll
        for (int k = 15; k >= 0; k--) {
            float num = __shfl_sync(FULL, rhs,  k, 16);
            float den = __shfl_sync(FULL, a[k], k, 16);
            float xk = num * rcp_ap(den);
            if (o == k) z = xk;
            rhs -= a[k] * xk;
        }

        if (lane < 16) {
            float c0 = sm[SM_M + wid*272 + o];   // M[o][0]
            out[((size_t)(b0 + wid)*2 + s)*16 + o] = c0 * det * z;
        }
    }
}

extern "C" void kernel_launch(void* const* d_in, const int* in_sizes, int n_in,
                              void* d_out, int out_size)
{
    const float* eq  = (const float*)d_in[0];
    const float* rei = (const float*)d_in[1];
    const float* W   = (const float*)d_in[2];
    const float* b   = (const float*)d_in[3];
    const float* ed  = (const float*)d_in[4];
    const float* ei  = (const float*)d_in[5];
    float* out = (float*)d_out;

    int B = in_sizes[0] / (32 * 256);        // 4096
    dim3 grid((B / 8) * 2);                  // 8 batches x 1 spin per block
    ocae4<<<grid, THREADS>>>(eq, rei, W, b, ed, ei, out);
}

// round 7
// speedup vs baseline: 1.1017x; 1.1017x over previous
#include <cuda_runtime.h>

#define THREADS 64

// ---------- packed f32x2 helpers ----------
__device__ __forceinline__ unsigned long long pk2(float lo, float hi) {
    unsigned long long r;
    asm("mov.b64 %0, {%1, %2};" : "=l"(r) : "f"(lo), "f"(hi));
    return r;
}
__device__ __forceinline__ void upk2(unsigned long long v, float& lo, float& hi) {
    asm("mov.b64 {%0, %1}, %2;" : "=f"(lo), "=f"(hi) : "l"(v));
}
__device__ __forceinline__ void ffma2(unsigned long long& acc, unsigned long long a, unsigned long long b) {
    asm("fma.rn.f32x2 %0, %1, %2, %0;" : "+l"(acc) : "l"(a), "l"(b));
}
__device__ __forceinline__ unsigned long long mul2(unsigned long long a, unsigned long long b) {
    unsigned long long r; asm("mul.rn.f32x2 %0, %1, %2;" : "=l"(r) : "l"(a), "l"(b)); return r;
}
__device__ __forceinline__ unsigned long long add2(unsigned long long a, unsigned long long b) {
    unsigned long long r; asm("add.rn.f32x2 %0, %1, %2;" : "=l"(r) : "l"(a), "l"(b)); return r;
}
__device__ __forceinline__ float sqrt_ap(float x){ float r; asm("sqrt.approx.f32 %0, %1;" : "=f"(r) : "f"(x)); return r; }
__device__ __forceinline__ float rcp_ap (float x){ float r; asm("rcp.approx.f32 %0, %1;"  : "=f"(r) : "f"(x)); return r; }

// smem float offsets:
//  W  [256][16]          4096
//  S  [8][8][12]         768   (A^T A sextets, o-pair interleaved)
//  EI [8][16]            128
//  B  [16]               16
//  M  [8][16*17]         2176  (M^T rows, stride 17)
//  X  [128 rows][16 k]   2048  (chunk staging, XOR-swizzled float4s)
#define SM_W  0
#define SM_S  4096
#define SM_EI 4864
#define SM_B  4992
#define SM_M  5008
#define SM_X  7184
#define SMEM_FLOATS 9232

__global__ __launch_bounds__(THREADS, 6)
void ocae5(const float* __restrict__ eq,  const float* __restrict__ rei,
           const float* __restrict__ Wg,  const float* __restrict__ bias,
           const float* __restrict__ envdim, const float* __restrict__ envion,
           float* __restrict__ out)
{
    __shared__ float sm[SMEM_FLOATS];
    const int tid = threadIdx.x;
    const int s   = blockIdx.x & 1;
    const int b0  = (blockIdx.x >> 1) * 8;   // 8 batches (128 rows) per block

    // ---------------- stage W, S, EI, B ----------------
    {
        const float4* Wsrc = (const float4*)(Wg + (size_t)s * 4096);
        #pragma unroll
        for (int i = 0; i < 16; i++)
            *(float4*)(sm + SM_W + (tid + 64*i)*4) = __ldg(Wsrc + tid + 64*i);

        #pragma unroll
        for (int u = 0; u < 2; u++) {
            int idx = tid + 64*u;
            sm[SM_EI + idx] = envion[s*128 + idx];
            int ii = idx >> 4, oo = idx & 15;
            const float* A = envdim + s*1152 + ii*144 + oo*9;
            float a00=A[0],a01=A[1],a02=A[2], a10=A[3],a11=A[4],a12=A[5], a20=A[6],a21=A[7],a22=A[8];
            float s00 = a00*a00 + a10*a10 + a20*a20;
            float s11 = a01*a01 + a11*a11 + a21*a21;
            float s22 = a02*a02 + a12*a12 + a22*a22;
            float s01 = 2.f*(a00*a01 + a10*a11 + a20*a21);
            float s02 = 2.f*(a00*a02 + a10*a12 + a20*a22);
            float s12 = 2.f*(a01*a02 + a11*a12 + a21*a22);
            float* dst = sm + SM_S + (ii*8 + (oo>>1))*12 + (oo&1);
            dst[0]=s00; dst[2]=s11; dst[4]=s22; dst[6]=s01; dst[8]=s02; dst[10]=s12;
        }
        if (tid < 16) sm[SM_B + tid] = bias[s*16 + tid];
    }

    const int rb = tid & 31;     // row slot base (warp lane)
    const int h  = tid >> 5;     // orbital half: orbs [8h, 8h+8)

    // per-thread row constants (rows rb, rb+32, rb+64, rb+96)
    int xbase[4], xsw[4];
    size_t grow[4];
    #pragma unroll
    for (int j = 0; j < 4; j++) {
        int r = rb + 32*j;
        grow[j]  = ((size_t)(b0 + (r>>4)))*32 + s*16 + (r&15);
        xbase[j] = SM_X + r*16;
        xsw[j]   = (r>>1) & 3;
    }

    // GEMM staging pointers: thread handles float4 g = tid + 64*jj of each 16-k chunk
    const float4* gptr[8];
    int soff[8];
    #pragma unroll
    for (int jj = 0; jj < 8; jj++) {
        int g  = tid + 64*jj;
        int q  = g & 3;            // f4 column within chunk
        int rs = g >> 2;           // row slot 0..127
        size_t gr = ((size_t)(b0 + (rs>>4)))*32 + s*16 + (rs&15);
        gptr[jj] = (const float4*)eq + gr*64 + q;
        soff[jj] = SM_X + rs*16 + ((q ^ ((rs>>1)&3)) << 2);
    }

    float4 pre[8];
    #pragma unroll
    for (int jj = 0; jj < 8; jj++) pre[jj] = __ldg(gptr[jj]);   // chunk 0

    __syncthreads();   // constants staged

    unsigned long long acc[16];
    #pragma unroll
    for (int i = 0; i < 16; i++) acc[i] = 0ull;

    // ---------------- GEMM: 16 chunks of 16 k ----------------
    for (int c = 0; c < 16; c++) {
        #pragma unroll
        for (int jj = 0; jj < 8; jj++)
            *(float4*)(sm + soff[jj]) = pre[jj];
        __syncthreads();

        if (c < 15) {
            #pragma unroll
            for (int jj = 0; jj < 8; jj++) pre[jj] = __ldg(gptr[jj] + (c+1)*4);
        }

        #pragma unroll
        for (int kq = 0; kq < 4; kq++) {
            float xv[4][4];
            #pragma unroll
            for (int j = 0; j < 4; j++)
                *(float4*)xv[j] = *(const float4*)(sm + xbase[j] + ((kq ^ xsw[j]) << 2));
            #pragma unroll
            for (int e = 0; e < 4; e++) {
                const ulonglong2* wp = (const ulonglong2*)(sm + SM_W + (c*16 + kq*4 + e)*16 + h*8);
                ulonglong2 wA = wp[0], wB = wp[1];
                #pragma unroll
                for (int j = 0; j < 4; j++) {
                    unsigned long long xx = pk2(xv[j][e], xv[j][e]);
                    ffma2(acc[j*4+0], xx, wA.x);
                    ffma2(acc[j*4+1], xx, wA.y);
                    ffma2(acc[j*4+2], xx, wB.x);
                    ffma2(acc[j*4+3], xx, wB.y);
                }
            }
        }
        __syncthreads();
    }

    // ---------------- env + M (thread keeps its own accumulators) ----------------
    #pragma unroll 1
    for (int j = 0; j < 4; j++) {
        float rv[24];
        {
            const float4* rp = (const float4*)rei + grow[j]*6;
            #pragma unroll
            for (int q = 0; q < 6; q++) *(float4*)(rv + q*4) = __ldg(rp + q);
        }
        unsigned long long ev[4] = {0,0,0,0};
        #pragma unroll
        for (int i = 0; i < 8; i++) {
            float r0 = rv[i*3], r1 = rv[i*3+1], r2 = rv[i*3+2];
            unsigned long long p00 = pk2(r0*r0, r0*r0);
            unsigned long long p11 = pk2(r1*r1, r1*r1);
            unsigned long long p22 = pk2(r2*r2, r2*r2);
            unsigned long long p01 = pk2(r0*r1, r0*r1);
            unsigned long long p02 = pk2(r0*r2, r0*r2);
            unsigned long long p12 = pk2(r1*r2, r1*r2);
            const float* Sb = sm + SM_S + i*96 + h*48;
            const unsigned long long* Eb = (const unsigned long long*)(sm + SM_EI) + i*8 + h*4;
            #pragma unroll
            for (int op = 0; op < 4; op++) {
                const ulonglong2* Sp = (const ulonglong2*)(Sb + op*12);
                ulonglong2 sA = Sp[0], sB = Sp[1], sC = Sp[2];
                unsigned long long q = 0ull;
                ffma2(q, sA.x, p00); ffma2(q, sA.y, p11); ffma2(q, sB.x, p22);
                ffma2(q, sB.y, p01); ffma2(q, sC.x, p02); ffma2(q, sC.y, p12);
                float q0, q1; upk2(q, q0, q1);
                float e0 = __expf(-sqrt_ap(fmaxf(q0, 0.f)));
                float e1 = __expf(-sqrt_ap(fmaxf(q1, 0.f)));
                ffma2(ev[op], pk2(e0, e1), Eb[op]);
            }
        }
        const int r = rb + 32*j;
        const int m = r >> 4, n = r & 15;
        float* Mb = sm + SM_M + m*272 + n;
        #pragma unroll
        for (int op = 0; op < 4; op++) {
            unsigned long long bb = *(const unsigned long long*)(sm + SM_B + (h*4+op)*2);
            unsigned long long mm = mul2(add2(acc[j*4+op], bb), ev[op]);
            float m0, m1; upk2(mm, m0, m1);
            Mb[(h*8 + 2*op)*17]     = m0;
            Mb[(h*8 + 2*op + 1)*17] = m1;
        }
    }
    __syncthreads();

    // ---------------- cofactors: register LU, 2 passes x 2 segments per warp ----------------
    const unsigned FULL = 0xffffffffu;
    const int lane = tid & 31;
    const int w    = tid >> 5;
    const int seg  = lane >> 4;
    const int o    = lane & 15;

    #pragma unroll 1
    for (int ip = 0; ip < 2; ip++) {
        const int m = w*4 + ip*2 + seg;
        float a[17];
        {
            const float* Ma = sm + SM_M + m*272 + o*17;
            #pragma unroll
            for (int j = 0; j < 16; j++) a[j] = Ma[j];
            a[16] = (o == 0) ? 1.f : 0.f;    // rhs e0
        }
        float det = 1.f;

        #pragma unroll
        for (int k = 0; k < 16; k++) {
            float v = (o >= k) ? fabsf(a[k]) : -1.f;
            int   p = o;
            #pragma unroll
            for (int off = 8; off; off >>= 1) {
                float ov = __shfl_xor_sync(FULL, v, off, 16);
                int   oq = __shfl_xor_sync(FULL, p, off, 16);
                if (ov > v || (ov == v && oq < p)) { v = ov; p = oq; }
            }
            float pvk = __shfl_sync(FULL, a[k], p, 16);
            float kvk = __shfl_sync(FULL, a[k], k, 16);
            if (o == k) a[k] = pvk; else if (o == p) a[k] = kvk;
            det = (p != k) ? -det : det;
            det *= pvk;
            float mlt = (o > k) ? a[k] * rcp_ap(pvk) : 0.f;
            #pragma unroll
            for (int j = k + 1; j < 17; j++) {
                float pv = __shfl_sync(FULL, a[j], p, 16);
                float kv = __shfl_sync(FULL, a[j], k, 16);
                if (o == k) a[j] = pv; else if (o == p) a[j] = kv;
                a[j] -= mlt * pv;
            }
        }

        // back-substitution: U z = rhs
        float z = 0.f, rhs = a[16];
        #pragma unroll
        for (int k = 15; k >= 0; k--) {
            float num = __shfl_sync(FULL, rhs,  k, 16);
            float den = __shfl_sync(FULL, a[k], k, 16);
            float xk = num * rcp_ap(den);
            if (o == k) z = xk;
            rhs -= a[k] * xk;
        }

        float c0 = sm[SM_M + m*272 + o];   // M[o][0]
        out[((size_t)(b0 + m)*2 + s)*16 + o] = c0 * det * z;
    }
}

extern "C" void kernel_launch(void* const* d_in, const int* in_sizes, int n_in,
                              void* d_out, int out_size)
{
    const float* eq  = (const float*)d_in[0];
    const float* rei = (const float*)d_in[1];
    const float* W   = (const float*)d_in[2];
    const float* b   = (const float*)d_in[3];
    const float* ed  = (const float*)d_in[4];
    const float* ei  = (const float*)d_in[5];
    float* out = (float*)d_out;

    int B = in_sizes[0] / (32 * 256);        // 4096
    dim3 grid((B / 8) * 2);                  // 8 batches x 1 spin per block
    ocae5<<<grid, THREADS>>>(eq, rei, W, b, ed, ei, out);
}